// round 6
// baseline (speedup 1.0000x reference)
#include <cuda_runtime.h>
#include <cuda_bf16.h>
#include <cstdint>

#define B_ 128
#define T_ 2048
#define DP_ 256
#define DQ_ 256
#define DO_ 256
#define TT 64
#define NTILES (T_ / TT)
#define QSTR 132
#define NTHR 512

// smem word offsets
#define WSH_OFF 0
#define Q0_OFF  32768
#define Q1_OFF  (Q0_OFF + TT * QSTR)      // 41216
#define WG_OFF  (Q1_OFF + TT * QSTR)      // 49664 (16B aligned)
#define E_OFF   (WG_OFF + 512)            // 50176
#define AP_OFF  (E_OFF + 64)              // 50240: [2][64][4]
#define ZB_OFF  (AP_OFF + 512)            // 50752: [2][256]
#define RED_OFF (ZB_OFF + 512)            // 51264
#define SMEM_WORDS (RED_OFF + 8)

__device__ float g_gpr[B_ * DO_];

__device__ __forceinline__ float fast_tanh(float x) {
    float y;
    asm("tanh.approx.f32 %0, %1;" : "=f"(y) : "f"(x));
    return y;
}

// ---------------- Kernel A: gpr[b,d] = cat(p,h)[b] . W_p_r[d] + b_p_r[d] + b_q[d]
__global__ void kA_gpr(const float* __restrict__ input_p,
                       const float* __restrict__ h_tm1,
                       const float* __restrict__ W_p_r,
                       const float* __restrict__ b_p_r,
                       const float* __restrict__ b_q) {
    __shared__ float ph[DP_ + DO_];
    int b = blockIdx.x, tid = threadIdx.x;
    ph[tid]       = input_p[b * DP_ + tid];
    ph[DP_ + tid] = h_tm1[b * DO_ + tid];
    __syncthreads();
    const float4* Wrow = reinterpret_cast<const float4*>(W_p_r + (size_t)tid * (DP_ + DO_));
    float a0 = 0.f, a1 = 0.f, a2 = 0.f, a3 = 0.f;
#pragma unroll 8
    for (int k4 = 0; k4 < (DP_ + DO_) / 4; ++k4) {
        float4 wv = Wrow[k4];
        a0 += wv.x * ph[k4 * 4 + 0];
        a1 += wv.y * ph[k4 * 4 + 1];
        a2 += wv.z * ph[k4 * 4 + 2];
        a3 += wv.w * ph[k4 * 4 + 3];
    }
    g_gpr[b * DO_ + tid] = b_p_r[tid] + b_q[tid] + ((a0 + a1) + (a2 + a3));
}

// ---------------- Fused, warp-specialized:
// warps 0-7  (compute): MMA m32xn64 + tanh·w epilogue for tile i
// warps 8-15 (data):    exp/mask + z-update for tile i-1, LDG+STS for tile i+1
__global__ __launch_bounds__(NTHR, 1)
void kFused(const float* __restrict__ input_q,
            const float* __restrict__ W_q,
            const float* __restrict__ wvec,
            const float* __restrict__ match_b,
            const int* __restrict__ mask_q,
            const float* __restrict__ input_p,
            float* __restrict__ out) {
    extern __shared__ uint32_t sh[];
    uint32_t* Wsh = sh + WSH_OFF;
    float2* wg_sh = reinterpret_cast<float2*>(sh + WG_OFF);   // {w[d], gpr[d]}
    float*  e_sh  = reinterpret_cast<float*>(sh + E_OFF);
    float*  ap_sh = reinterpret_cast<float*>(sh + AP_OFF);    // [2][64][4]
    float*  zbuf  = reinterpret_cast<float*>(sh + ZB_OFF);    // [2][256]
    float*  red   = reinterpret_cast<float*>(sh + RED_OFF);

    int b    = blockIdx.x;
    int tid  = threadIdx.x;
    int lane = tid & 31, wid = tid >> 5;

    // ---- W (fp32) -> bf16 SMEM, 16B-chunk XOR swizzle
    for (int i = tid; i < 256 * 128; i += NTHR) {
        int n = i >> 7, kw = i & 127;
        float2 f = reinterpret_cast<const float2*>(W_q)[n * 128 + kw];
        __nv_bfloat162 h = __floats2bfloat162_rn(f.x, f.y);
        int chunk = kw >> 2;
        int phys  = chunk ^ (n & 7);
        Wsh[n * 128 + phys * 4 + (kw & 3)] = *reinterpret_cast<uint32_t*>(&h);
    }
    if (tid < DO_) wg_sh[tid] = make_float2(wvec[tid], g_gpr[b * DO_ + tid]);

    const float   mb  = match_b[0];
    const float4* qb4 = reinterpret_cast<const float4*>(input_q + (size_t)b * T_ * DQ_);
    const int*    mqb = mask_q + (size_t)b * T_;

    // ---- tile 0 -> Qsh0 (all 512 threads)
#pragma unroll
    for (int j = 0; j < 8; ++j) {
        int idx = tid + j * NTHR;
        float4 f = qb4[idx];
        int row = idx >> 6, c4 = idx & 63;
        __nv_bfloat162 h0 = __floats2bfloat162_rn(f.x, f.y);
        __nv_bfloat162 h1 = __floats2bfloat162_rn(f.z, f.w);
        sh[Q0_OFF + row * QSTR + c4 * 2]     = *reinterpret_cast<uint32_t*>(&h0);
        sh[Q0_OFF + row * QSTR + c4 * 2 + 1] = *reinterpret_cast<uint32_t*>(&h1);
    }
    __syncthreads();

    // persistent per-thread state
    float Sth = 0.f, Mth = -1e30f;        // data threads dtid<64
    float z0 = 0.f, z1 = 0.f;             // data threads
    int   mprev = 0;

    int warp_m = wid & 1, warp_n = wid >> 1;          // compute mapping
    int dtid = tid - 256;                              // data mapping
    int zword = dtid & 127, zhalf = dtid >> 7;

    for (int it = 0; it <= NTILES; ++it) {
        if (tid < 256) {
            // ================= COMPUTE WARPS =================
            if (it < NTILES) {
                const uint32_t* Qcur = sh + ((it & 1) ? Q1_OFF : Q0_OFF);
                float c[16][4];
#pragma unroll
                for (int q = 0; q < 16; ++q) { c[q][0] = c[q][1] = c[q][2] = c[q][3] = 0.f; }

#pragma unroll 4
                for (int kc = 0; kc < 16; ++kc) {
                    uint32_t a[2][4];
#pragma unroll
                    for (int mt = 0; mt < 2; ++mt) {
                        int arow = warp_m * 32 + mt * 16 + (lane & 15);
                        int acol = kc * 8 + ((lane & 16) ? 4 : 0);
                        uint32_t aaddr = (uint32_t)__cvta_generic_to_shared(&Qcur[arow * QSTR + acol]);
                        asm volatile("ldmatrix.sync.aligned.m8n8.x4.shared.b16 {%0,%1,%2,%3}, [%4];"
                                     : "=r"(a[mt][0]), "=r"(a[mt][1]), "=r"(a[mt][2]), "=r"(a[mt][3])
                                     : "r"(aaddr));
                    }
#pragma unroll
                    for (int np = 0; np < 4; ++np) {
                        int row   = warp_n * 64 + np * 16 + (lane & 7) + ((lane & 16) ? 8 : 0);
                        int chunk = kc * 2 + ((lane & 8) ? 1 : 0);
                        int phys  = chunk ^ (row & 7);
                        uint32_t baddr = (uint32_t)__cvta_generic_to_shared(&Wsh[row * 128 + phys * 4]);
                        uint32_t b0, b1, b2, b3;
                        asm volatile("ldmatrix.sync.aligned.m8n8.x4.shared.b16 {%0,%1,%2,%3}, [%4];"
                                     : "=r"(b0), "=r"(b1), "=r"(b2), "=r"(b3) : "r"(baddr));
#pragma unroll
                        for (int mt = 0; mt < 2; ++mt) {
                            float* c0 = c[mt * 8 + np * 2];
                            float* c1 = c[mt * 8 + np * 2 + 1];
                            asm volatile(
                                "mma.sync.aligned.m16n8k16.row.col.f32.bf16.bf16.f32 "
                                "{%0,%1,%2,%3}, {%4,%5,%6,%7}, {%8,%9}, {%0,%1,%2,%3};"
                                : "+f"(c0[0]), "+f"(c0[1]), "+f"(c0[2]), "+f"(c0[3])
                                : "r"(a[mt][0]), "r"(a[mt][1]), "r"(a[mt][2]), "r"(a[mt][3]),
                                  "r"(b0), "r"(b1));
                            asm volatile(
                                "mma.sync.aligned.m16n8k16.row.col.f32.bf16.bf16.f32 "
                                "{%0,%1,%2,%3}, {%4,%5,%6,%7}, {%8,%9}, {%0,%1,%2,%3};"
                                : "+f"(c1[0]), "+f"(c1[1]), "+f"(c1[2]), "+f"(c1[3])
                                : "r"(a[mt][0]), "r"(a[mt][1]), "r"(a[mt][2]), "r"(a[mt][3]),
                                  "r"(b2), "r"(b3));
                        }
                    }
                }

                // ---- epilogue: tanh + dot(w), quad reduce, disjoint partial writes
                float* apb = ap_sh + (it & 1) * 256;
#pragma unroll
                for (int mt = 0; mt < 2; ++mt) {
                    float p0 = 0.f, p1 = 0.f;
#pragma unroll
                    for (int nt = 0; nt < 8; ++nt) {
                        int n = warp_n * 64 + nt * 8 + (lane & 3) * 2;
                        float4 wg = *reinterpret_cast<const float4*>(&wg_sh[n]);  // {w0,g0,w1,g1}
                        float* cc = c[mt * 8 + nt];
                        p0 += wg.x * fast_tanh(cc[0] + wg.y) + wg.z * fast_tanh(cc[1] + wg.w);
                        p1 += wg.x * fast_tanh(cc[2] + wg.y) + wg.z * fast_tanh(cc[3] + wg.w);
                    }
                    p0 += __shfl_xor_sync(0xffffffffu, p0, 1);
                    p0 += __shfl_xor_sync(0xffffffffu, p0, 2);
                    p1 += __shfl_xor_sync(0xffffffffu, p1, 1);
                    p1 += __shfl_xor_sync(0xffffffffu, p1, 2);
                    if ((lane & 3) == 0) {
                        int row0 = warp_m * 32 + mt * 16 + (lane >> 2);
                        apb[row0 * 4 + warp_n]       = p0;
                        apb[(row0 + 8) * 4 + warp_n] = p1;
                    }
                }
            }
        } else {
            // ================= DATA WARPS =================
            // mask for tile `it` (used next iteration as tile it's stage-1)
            int mnext = 0;
            if (it < NTILES && dtid < 64) mnext = mqb[it * TT + dtid];

            // LDG tile it+1 into registers
            bool ldg = (it + 1) < NTILES;
            float4 pf[16];
            if (ldg) {
                const float4* src = qb4 + (size_t)(it + 1) * TT * 64;
#pragma unroll
                for (int j = 0; j < 16; ++j) pf[j] = src[dtid + j * 256];
            }

            // stage 1 + z for tile it-1
            if (it > 0) {
                if (dtid < 64) {
                    const float* ap = &ap_sh[((it - 1) & 1) * 256 + dtid * 4];
                    float raw = (ap[0] + ap[1]) + (ap[2] + ap[3]) + mb;
                    float mflt = (float)mprev;
                    float x = fminf(fmaxf(raw, -15.f), 15.f) * mflt;
                    float e = __expf(x - 15.f) * mflt;
                    e_sh[dtid] = e;
                    Sth += e;
                    Mth = fmaxf(Mth, x);
                }
                asm volatile("bar.sync 1, 256;" ::: "memory");

                const uint32_t* Qold = sh + (((it - 1) & 1) ? Q1_OFF : Q0_OFF);
                float a0 = 0.f, a1 = 0.f;
                int tbase = zhalf * 32;
#pragma unroll 8
                for (int ttk = 0; ttk < 32; ++ttk) {
                    int t = tbase + ttk;
                    uint32_t qw = Qold[t * QSTR + zword];
                    __nv_bfloat162 h2 = *reinterpret_cast<__nv_bfloat162*>(&qw);
                    float e = e_sh[t];
                    a0 += e * __bfloat162float(__low2bfloat16(h2));
                    a1 += e * __bfloat162float(__high2bfloat16(h2));
                }
                z0 += a0;
                z1 += a1;
            }
            asm volatile("bar.sync 1, 256;" ::: "memory");  // z reads done before STS overwrites

            if (ldg) {
                uint32_t* Qn = sh + (((it + 1) & 1) ? Q1_OFF : Q0_OFF);
#pragma unroll
                for (int j = 0; j < 16; ++j) {
                    int idx = dtid + j * 256;
                    int row = idx >> 6, c4 = idx & 63;
                    __nv_bfloat162 h0 = __floats2bfloat162_rn(pf[j].x, pf[j].y);
                    __nv_bfloat162 h1 = __floats2bfloat162_rn(pf[j].z, pf[j].w);
                    *reinterpret_cast<uint2*>(&Qn[row * QSTR + c4 * 2]) =
                        make_uint2(*reinterpret_cast<uint32_t*>(&h0),
                                   *reinterpret_cast<uint32_t*>(&h1));
                }
            }
            mprev = mnext;
        }
        __syncthreads();
    }

    // ---- final reductions
    if (tid >= 256) {
        if (dtid < 64) {
            float s = Sth, m = Mth;
#pragma unroll
            for (int o = 16; o; o >>= 1) {
                s += __shfl_xor_sync(0xffffffffu, s, o);
                m = fmaxf(m, __shfl_xor_sync(0xffffffffu, m, o));
            }
            if (lane == 0) { red[dtid >> 5] = s; red[2 + (dtid >> 5)] = m; }
        }
        zbuf[zhalf * 256 + zword * 2]     = z0;
        zbuf[zhalf * 256 + zword * 2 + 1] = z1;
    }
    __syncthreads();

    if (tid < 256) {
        float Sp = red[0] + red[1];
        float Mg = fmaxf(red[2], red[3]);
        float denom = Sp + 1e-6f * __expf(Mg - 15.f);
        float zt = zbuf[tid] + zbuf[256 + tid];
        out[b * (DP_ + DQ_) + tid]       = input_p[b * DP_ + tid];
        out[b * (DP_ + DQ_) + DP_ + tid] = zt / denom;
    }
}

extern "C" void kernel_launch(void* const* d_in, const int* in_sizes, int n_in,
                              void* d_out, int out_size) {
    const float* input_p = (const float*)d_in[0];
    const float* input_q = (const float*)d_in[2];
    const int*   mask_q  = (const int*)d_in[3];
    const float* h_tm1   = (const float*)d_in[4];
    const float* W_p_r   = (const float*)d_in[5];
    const float* b_p_r   = (const float*)d_in[6];
    const float* W_q     = (const float*)d_in[7];
    const float* b_q     = (const float*)d_in[8];
    const float* wv      = (const float*)d_in[9];
    const float* match_b = (const float*)d_in[10];
    float* out = (float*)d_out;

    kA_gpr<<<B_, 256>>>(input_p, h_tm1, W_p_r, b_p_r, b_q);

    size_t smemF = (size_t)SMEM_WORDS * 4;
    cudaFuncSetAttribute(kFused, cudaFuncAttributeMaxDynamicSharedMemorySize, (int)smemF);
    kFused<<<B_, NTHR, smemF>>>(input_q, W_q, wv, match_b, mask_q, input_p, out);
}

// round 7
// speedup vs baseline: 1.0513x; 1.0513x over previous
#include <cuda_runtime.h>
#include <cuda_bf16.h>
#include <cstdint>

#define B_ 128
#define T_ 2048
#define DP_ 256
#define DQ_ 256
#define DO_ 256
#define TT 128
#define NTILES (T_ / TT)
#define NTHR 512

// smem word offsets
#define WSH_OFF 0          // 32768 words: W bf16, 128 words/row, XOR swizzle
#define Q_OFF   32768      // 16384 words: Q tile bf16, 128 words/row packed, XOR swizzle
#define WG_OFF  49152      // 512 words: float2 {w[d], gpr[d]}
#define E_OFF   49664      // 128 words
#define AP_OFF  49792      // 512 words: alpha_part[128][4]
#define ZB_OFF  50304      // 1024 words: zbuf[4][256] (also ph[512] in prologue)
#define RED_OFF 51328      // 8 words
#define SMEM_WORDS 51336

__device__ __forceinline__ float fast_tanh(float x) {
    float y;
    asm("tanh.approx.f32 %0, %1;" : "=f"(y) : "f"(x));
    return y;
}

__global__ __launch_bounds__(NTHR, 1)
void kFused(const float* __restrict__ input_q,
            const float* __restrict__ W_q,
            const float* __restrict__ wvec,
            const float* __restrict__ match_b,
            const int* __restrict__ mask_q,
            const float* __restrict__ input_p,
            const float* __restrict__ h_tm1,
            const float* __restrict__ W_p_r,
            const float* __restrict__ b_p_r,
            const float* __restrict__ b_q,
            float* __restrict__ out) {
    extern __shared__ uint32_t sh[];
    uint32_t* Wsh = sh + WSH_OFF;
    float2* wg_sh = reinterpret_cast<float2*>(sh + WG_OFF);
    float*  e_sh  = reinterpret_cast<float*>(sh + E_OFF);
    float*  ap_sh = reinterpret_cast<float*>(sh + AP_OFF);
    float*  zbuf  = reinterpret_cast<float*>(sh + ZB_OFF);
    float*  red   = reinterpret_cast<float*>(sh + RED_OFF);

    int b    = blockIdx.x;
    int tid  = threadIdx.x;
    int lane = tid & 31, wid = tid >> 5;

    // ================= Prologue =================
    // ph = [input_p | h_tm1] into zbuf
    if (tid < 256) zbuf[tid]       = input_p[b * 256 + tid];
    else           zbuf[tid]       = h_tm1[b * 256 + (tid - 256)];
    __syncthreads();

    // gpr[d] = W_p_r[d,:] . ph + b_p_r[d] + b_q[d]; warp wid owns rows wid*16..+15
    for (int r = 0; r < 16; ++r) {
        int d = wid * 16 + r;
        const float4* row = reinterpret_cast<const float4*>(W_p_r + (size_t)d * 512);
        const float4* p4  = reinterpret_cast<const float4*>(zbuf);
        float acc = 0.f;
#pragma unroll
        for (int i = 0; i < 4; ++i) {
            float4 wv = row[i * 32 + lane];
            float4 pv = p4[i * 32 + lane];
            acc += wv.x * pv.x + wv.y * pv.y + wv.z * pv.z + wv.w * pv.w;
        }
#pragma unroll
        for (int o = 16; o; o >>= 1) acc += __shfl_xor_sync(0xffffffffu, acc, o);
        if (lane == 0) wg_sh[d] = make_float2(wvec[d], acc + b_p_r[d] + b_q[d]);
    }

    // W_q (fp32) -> bf16 SMEM, 16B-chunk XOR swizzle (128 words/row)
    for (int i = tid; i < 256 * 128; i += NTHR) {
        int n = i >> 7, kw = i & 127;
        float2 f = reinterpret_cast<const float2*>(W_q)[n * 128 + kw];
        __nv_bfloat162 h = __floats2bfloat162_rn(f.x, f.y);
        int phys = (kw >> 2) ^ (n & 7);
        Wsh[n * 128 + phys * 4 + (kw & 3)] = *reinterpret_cast<uint32_t*>(&h);
    }

    const float   mb  = match_b[0];
    const float4* qb4 = reinterpret_cast<const float4*>(input_q + (size_t)b * T_ * DQ_);
    const int*    mqb = mask_q + (size_t)b * T_;

    // Q tile 0 -> smem (packed 128 words/row, XOR swizzle on 16B chunks)
#pragma unroll
    for (int j = 0; j < 16; ++j) {
        int idx = tid + j * NTHR;
        float4 f = qb4[idx];
        int row = idx >> 6, c4 = idx & 63;
        __nv_bfloat162 h0 = __floats2bfloat162_rn(f.x, f.y);
        __nv_bfloat162 h1 = __floats2bfloat162_rn(f.z, f.w);
        uint32_t phys = (uint32_t)(c4 >> 1) ^ (uint32_t)(row & 7);
        *reinterpret_cast<uint2*>(&sh[Q_OFF + row * 128 + phys * 4 + (c4 & 1) * 2]) =
            make_uint2(*reinterpret_cast<uint32_t*>(&h0), *reinterpret_cast<uint32_t*>(&h1));
    }
    __syncthreads();

    // ================= Main loop =================
    int warp_m = wid & 3;        // 4 warps over 128 rows (32 each)
    int warp_n = wid >> 2;       // 4 warps over 256 cols (64 each)
    int zw = tid & 127;          // z word (d pair)
    int zq = tid >> 7;           // t quarter (32 tokens)
    int zc = zw >> 2, zr = zw & 3;

    float Sth = 0.f, Mth = -1e30f;      // stage-1 threads (tid<128)
    float z0 = 0.f, z1 = 0.f;

    for (int it = 0; it < NTILES; ++it) {
        // mask for this tile (latency hidden under MMA)
        int mreg = 0;
        if (tid < 128) mreg = mqb[it * TT + tid];

        bool has_next = (it + 1 < NTILES);
        const float4* src = qb4 + (size_t)(it + 1) * TT * 64;

        // ---- MMA: C[128 x 256] = Qtile @ W^T, warp tile m32 x n64
        float c[16][4];
#pragma unroll
        for (int q = 0; q < 16; ++q) { c[q][0] = c[q][1] = c[q][2] = c[q][3] = 0.f; }

#pragma unroll 4
        for (int kc = 0; kc < 16; ++kc) {
            uint32_t a[2][4];
#pragma unroll
            for (int mt = 0; mt < 2; ++mt) {
                int arow  = warp_m * 32 + mt * 16 + (lane & 15);
                int physA = (kc * 2 + ((lane & 16) ? 1 : 0)) ^ (arow & 7);
                uint32_t aaddr = (uint32_t)__cvta_generic_to_shared(
                    &sh[Q_OFF + arow * 128 + physA * 4]);
                asm volatile("ldmatrix.sync.aligned.m8n8.x4.shared.b16 {%0,%1,%2,%3}, [%4];"
                             : "=r"(a[mt][0]), "=r"(a[mt][1]), "=r"(a[mt][2]), "=r"(a[mt][3])
                             : "r"(aaddr));
            }
#pragma unroll
            for (int np = 0; np < 4; ++np) {
                int row   = warp_n * 64 + np * 16 + (lane & 7) + ((lane & 16) ? 8 : 0);
                int physB = (kc * 2 + ((lane & 8) ? 1 : 0)) ^ (row & 7);
                uint32_t baddr = (uint32_t)__cvta_generic_to_shared(
                    &Wsh[row * 128 + physB * 4]);
                uint32_t b0, b1, b2, b3;
                asm volatile("ldmatrix.sync.aligned.m8n8.x4.shared.b16 {%0,%1,%2,%3}, [%4];"
                             : "=r"(b0), "=r"(b1), "=r"(b2), "=r"(b3) : "r"(baddr));
#pragma unroll
                for (int mt = 0; mt < 2; ++mt) {
                    float* c0 = c[mt * 8 + np * 2];
                    float* c1 = c[mt * 8 + np * 2 + 1];
                    asm volatile(
                        "mma.sync.aligned.m16n8k16.row.col.f32.bf16.bf16.f32 "
                        "{%0,%1,%2,%3}, {%4,%5,%6,%7}, {%8,%9}, {%0,%1,%2,%3};"
                        : "+f"(c0[0]), "+f"(c0[1]), "+f"(c0[2]), "+f"(c0[3])
                        : "r"(a[mt][0]), "r"(a[mt][1]), "r"(a[mt][2]), "r"(a[mt][3]),
                          "r"(b0), "r"(b1));
                    asm volatile(
                        "mma.sync.aligned.m16n8k16.row.col.f32.bf16.bf16.f32 "
                        "{%0,%1,%2,%3}, {%4,%5,%6,%7}, {%8,%9}, {%0,%1,%2,%3};"
                        : "+f"(c1[0]), "+f"(c1[1]), "+f"(c1[2]), "+f"(c1[3])
                        : "r"(a[mt][0]), "r"(a[mt][1]), "r"(a[mt][2]), "r"(a[mt][3]),
                          "r"(b2), "r"(b3));
                }
            }
        }

        // ---- prefetch chunk1 (rows 0..63 of next tile); latency covered by epilogue
        float4 pf1[8];
        if (has_next) {
#pragma unroll
            for (int j = 0; j < 8; ++j) pf1[j] = src[tid + j * NTHR];
        }

        // ---- epilogue: tanh + dot(w), quad reduce, disjoint partial writes
#pragma unroll
        for (int mt = 0; mt < 2; ++mt) {
            float p0 = 0.f, p1 = 0.f;
#pragma unroll
            for (int nt = 0; nt < 8; ++nt) {
                int n = warp_n * 64 + nt * 8 + (lane & 3) * 2;
                float4 wg = *reinterpret_cast<const float4*>(&wg_sh[n]);  // {w0,g0,w1,g1}
                float* cc = c[mt * 8 + nt];
                p0 += wg.x * fast_tanh(cc[0] + wg.y) + wg.z * fast_tanh(cc[1] + wg.w);
                p1 += wg.x * fast_tanh(cc[2] + wg.y) + wg.z * fast_tanh(cc[3] + wg.w);
            }
            p0 += __shfl_xor_sync(0xffffffffu, p0, 1);
            p0 += __shfl_xor_sync(0xffffffffu, p0, 2);
            p1 += __shfl_xor_sync(0xffffffffu, p1, 1);
            p1 += __shfl_xor_sync(0xffffffffu, p1, 2);
            if ((lane & 3) == 0) {
                int row0 = warp_m * 32 + mt * 16 + (lane >> 2);
                ap_sh[row0 * 4 + warp_n]       = p0;
                ap_sh[(row0 + 8) * 4 + warp_n] = p1;
            }
        }
        __syncthreads();   // S1: alpha partials ready

        // ---- prefetch chunk2 (rows 64..127); latency covered by stage1 + z-phase
        float4 pf2[8];
        if (has_next) {
#pragma unroll
            for (int j = 0; j < 8; ++j) pf2[j] = src[tid + (j + 8) * NTHR];
        }

        // ---- stage 1 (threads 0..127): e = exp(x-15)*m ; accumulate S, M
        if (tid < 128) {
            float4 ap = *reinterpret_cast<float4*>(&ap_sh[tid * 4]);
            float raw = (ap.x + ap.y) + (ap.z + ap.w) + mb;
            float mflt = (float)mreg;
            float x = fminf(fmaxf(raw, -15.f), 15.f) * mflt;
            float e = __expf(x - 15.f) * mflt;
            e_sh[tid] = e;
            Sth += e;
            Mth = fmaxf(Mth, x);
        }
        __syncthreads();   // S2: e_sh ready

        // ---- z update: thread owns d pair zw, t-quarter zq (32 tokens)
        {
            float a0 = 0.f, a1 = 0.f;
            int tb = zq * 32;
#pragma unroll 8
            for (int k = 0; k < 32; ++k) {
                int t = tb + k;
                uint32_t qw = sh[Q_OFF + t * 128 + (((uint32_t)zc ^ (uint32_t)(t & 7)) << 2) + zr];
                __nv_bfloat162 h2 = *reinterpret_cast<__nv_bfloat162*>(&qw);
                float e = e_sh[t];
                a0 += e * __bfloat162float(__low2bfloat16(h2));
                a1 += e * __bfloat162float(__high2bfloat16(h2));
            }
            z0 += a0;
            z1 += a1;
        }
        __syncthreads();   // S3: Q reads done, buffer free

        // ---- store next tile
        if (has_next) {
#pragma unroll
            for (int j = 0; j < 16; ++j) {
                int idx = tid + j * NTHR;
                float4 f = (j < 8) ? pf1[j & 7] : pf2[j & 7];
                int row = idx >> 6, c4 = idx & 63;
                __nv_bfloat162 h0 = __floats2bfloat162_rn(f.x, f.y);
                __nv_bfloat162 h1 = __floats2bfloat162_rn(f.z, f.w);
                uint32_t phys = (uint32_t)(c4 >> 1) ^ (uint32_t)(row & 7);
                *reinterpret_cast<uint2*>(&sh[Q_OFF + row * 128 + phys * 4 + (c4 & 1) * 2]) =
                    make_uint2(*reinterpret_cast<uint32_t*>(&h0), *reinterpret_cast<uint32_t*>(&h1));
            }
        }
        __syncthreads();   // S4: buffer ready for next MMA
    }

    // ================= Final =================
    if (tid < 128) {
        float s = Sth, m = Mth;
#pragma unroll
        for (int o = 16; o; o >>= 1) {
            s += __shfl_xor_sync(0xffffffffu, s, o);
            m = fmaxf(m, __shfl_xor_sync(0xffffffffu, m, o));
        }
        if (lane == 0) { red[wid] = s; red[4 + wid] = m; }
    }
    zbuf[zq * 256 + zw * 2]     = z0;
    zbuf[zq * 256 + zw * 2 + 1] = z1;
    __syncthreads();

    if (tid < 256) {
        float Sp = (red[0] + red[1]) + (red[2] + red[3]);
        float Mg = fmaxf(fmaxf(red[4], red[5]), fmaxf(red[6], red[7]));
        float denom = Sp + 1e-6f * __expf(Mg - 15.f);
        float zt = (zbuf[tid] + zbuf[256 + tid]) + (zbuf[512 + tid] + zbuf[768 + tid]);
        out[b * (DP_ + DQ_) + tid]       = input_p[b * DP_ + tid];
        out[b * (DP_ + DQ_) + DP_ + tid] = zt / denom;
    }
}

extern "C" void kernel_launch(void* const* d_in, const int* in_sizes, int n_in,
                              void* d_out, int out_size) {
    const float* input_p = (const float*)d_in[0];
    const float* input_q = (const float*)d_in[2];
    const int*   mask_q  = (const int*)d_in[3];
    const float* h_tm1   = (const float*)d_in[4];
    const float* W_p_r   = (const float*)d_in[5];
    const float* b_p_r   = (const float*)d_in[6];
    const float* W_q     = (const float*)d_in[7];
    const float* b_q     = (const float*)d_in[8];
    const float* wv      = (const float*)d_in[9];
    const float* match_b = (const float*)d_in[10];
    float* out = (float*)d_out;

    size_t smemF = (size_t)SMEM_WORDS * 4;
    cudaFuncSetAttribute(kFused, cudaFuncAttributeMaxDynamicSharedMemorySize, (int)smemF);
    kFused<<<B_, NTHR, smemF>>>(input_q, W_q, wv, match_b, mask_q,
                                input_p, h_tm1, W_p_r, b_p_r, b_q, out);
}